// round 1
// baseline (speedup 1.0000x reference)
#include <cuda_runtime.h>
#include <math.h>

// Problem constants (shapes are fixed by the dataset; N/M re-derived from sizes)
#define ZD      256     // Z_DIM
#define BT      128     // tile size in n and m
#define KC      32      // K chunk held in smem
#define NSPLIT  16      // split of the N dimension across blockIdx.y
#define MAXN    32768
#define MAXM    8192

// Scratch (no allocations allowed -> __device__ globals)
__device__ float g_a2[MAXN];
__device__ float g_b2[MAXM];
__device__ float g_pmax[NSPLIT * MAXM];
__device__ float g_psum[NSPLIT * MAXM];
__device__ float g_acc;

// sigma arrives as a python scalar; dtype (int32 vs float32) is ambiguous.
// Heuristic: reinterpret bits as float; if that is a sane magnitude it was a
// float, otherwise treat the bits as an int. (int 1 -> 1.4e-45 -> int path.)
__device__ __forceinline__ float load_sigma(const void* p) {
    int   i = *(const int*)p;
    float f = __int_as_float(i);
    if (isfinite(f) && fabsf(f) >= 1e-10f && fabsf(f) <= 1e10f) return f;
    return (float)i;
}

// ---------------------------------------------------------------------------
// Row squared-norms: one warp per row
// ---------------------------------------------------------------------------
__global__ void rownorm_a_kernel(const float* __restrict__ X, int rows) {
    int w    = (blockIdx.x * blockDim.x + threadIdx.x) >> 5;
    int lane = threadIdx.x & 31;
    if (w >= rows) return;
    const float4* r = (const float4*)(X + (size_t)w * ZD);
    float s = 0.f;
    #pragma unroll
    for (int c = lane; c < ZD / 4; c += 32) {
        float4 v = r[c];
        s += v.x * v.x + v.y * v.y + v.z * v.z + v.w * v.w;
    }
    #pragma unroll
    for (int o = 16; o; o >>= 1) s += __shfl_xor_sync(0xffffffffu, s, o);
    if (lane == 0) g_a2[w] = s;
}

__global__ void rownorm_b_kernel(const float* __restrict__ X, int rows) {
    int w    = (blockIdx.x * blockDim.x + threadIdx.x) >> 5;
    int lane = threadIdx.x & 31;
    if (w >= rows) return;
    const float4* r = (const float4*)(X + (size_t)w * ZD);
    float s = 0.f;
    #pragma unroll
    for (int c = lane; c < ZD / 4; c += 32) {
        float4 v = r[c];
        s += v.x * v.x + v.y * v.y + v.z * v.z + v.w * v.w;
    }
    #pragma unroll
    for (int o = 16; o; o >>= 1) s += __shfl_xor_sync(0xffffffffu, s, o);
    if (lane == 0) g_b2[w] = s;
}

// ---------------------------------------------------------------------------
// Fused GEMM (mean @ e^T) + online logsumexp over the n-axis.
// Block: 256 threads (16x16), 8x8 register tile -> 128x128 S tile.
// grid.x = M/128 (m tile), grid.y = NSPLIT (n range). Each block maintains a
// running (max, sum) per m-column over its n-range; partials written out.
// ---------------------------------------------------------------------------
__global__ __launch_bounds__(256, 2)
void gemm_lse_kernel(const float* __restrict__ A,   // mean [N][ZD]
                     const float* __restrict__ B,   // e    [M][ZD]
                     const void* __restrict__ sigp,
                     int N, int M)
{
    __shared__ float As[KC][BT + 4];   // transposed: As[k][n]
    __shared__ float Bs[KC][BT + 4];   // transposed: Bs[k][m]
    __shared__ float red[16][BT];
    __shared__ float s_max[BT];
    __shared__ float s_scale[BT];
    __shared__ float run_max[BT];
    __shared__ float run_sum[BT];

    const int t  = threadIdx.x;
    const int tx = t & 15;
    const int ty = t >> 4;
    const int m0 = blockIdx.x * BT;
    const int split = blockIdx.y;

    const int ntiles    = N / BT;
    const int tiles_per = (ntiles + NSPLIT - 1) / NSPLIT;
    const int t_begin   = split * tiles_per;
    const int t_end     = min(t_begin + tiles_per, ntiles);

    const float sg      = load_sigma(sigp);
    const float inv2s2  = 1.0f / (2.0f * sg * sg);

    if (t < BT) { run_max[t] = -INFINITY; run_sum[t] = 0.0f; }
    __syncthreads();

    for (int nt = t_begin; nt < t_end; ++nt) {
        const int n0 = nt * BT;

        float acc[8][8];
        #pragma unroll
        for (int i = 0; i < 8; ++i)
            #pragma unroll
            for (int j = 0; j < 8; ++j) acc[i][j] = 0.0f;

        #pragma unroll 1
        for (int kc = 0; kc < ZD / KC; ++kc) {
            // Fill As/Bs (transposed) with float4 global loads
            #pragma unroll
            for (int it = 0; it < 4; ++it) {
                int idx = t + it * 256;       // 0..1023
                int row = idx >> 3;           // 0..127
                int kv  = idx & 7;            // float4 index in K chunk
                float4 a = *(const float4*)(A + (size_t)(n0 + row) * ZD + kc * KC + kv * 4);
                As[kv * 4 + 0][row] = a.x;
                As[kv * 4 + 1][row] = a.y;
                As[kv * 4 + 2][row] = a.z;
                As[kv * 4 + 3][row] = a.w;
                float4 b = *(const float4*)(B + (size_t)(m0 + row) * ZD + kc * KC + kv * 4);
                Bs[kv * 4 + 0][row] = b.x;
                Bs[kv * 4 + 1][row] = b.y;
                Bs[kv * 4 + 2][row] = b.z;
                Bs[kv * 4 + 3][row] = b.w;
            }
            __syncthreads();

            #pragma unroll
            for (int kk = 0; kk < KC; ++kk) {
                float ra[8], rb[8];
                #pragma unroll
                for (int i = 0; i < 8; ++i) ra[i] = As[kk][ty * 8 + i];
                #pragma unroll
                for (int j = 0; j < 8; ++j) rb[j] = Bs[kk][tx * 8 + j];
                #pragma unroll
                for (int i = 0; i < 8; ++i)
                    #pragma unroll
                    for (int j = 0; j < 8; ++j)
                        acc[i][j] = fmaf(ra[i], rb[j], acc[i][j]);
            }
            __syncthreads();
        }

        // logits (without the per-m b2 constant): t = (2*ab - a2_n) * inv2s2
        float a2r[8];
        #pragma unroll
        for (int i = 0; i < 8; ++i) a2r[i] = g_a2[n0 + ty * 8 + i];

        float lm[8];
        #pragma unroll
        for (int j = 0; j < 8; ++j) {
            float mx = -INFINITY;
            #pragma unroll
            for (int i = 0; i < 8; ++i) {
                float v = (2.0f * acc[i][j] - a2r[i]) * inv2s2;
                acc[i][j] = v;
                mx = fmaxf(mx, v);
            }
            lm[j] = mx;
        }
        #pragma unroll
        for (int j = 0; j < 8; ++j) red[ty][tx * 8 + j] = lm[j];
        __syncthreads();

        if (t < BT) {
            float cm = red[0][t];
            #pragma unroll
            for (int r = 1; r < 16; ++r) cm = fmaxf(cm, red[r][t]);
            float om = run_max[t];
            float nm = fmaxf(om, cm);
            s_max[t]   = nm;
            s_scale[t] = __expf(om - nm);   // om=-inf -> 0
            run_max[t] = nm;
        }
        __syncthreads();

        #pragma unroll
        for (int j = 0; j < 8; ++j) {
            float nm = s_max[tx * 8 + j];
            float s  = 0.0f;
            #pragma unroll
            for (int i = 0; i < 8; ++i) s += __expf(acc[i][j] - nm);
            red[ty][tx * 8 + j] = s;
        }
        __syncthreads();

        if (t < BT) {
            float cs = red[0][t];
            #pragma unroll
            for (int r = 1; r < 16; ++r) cs += red[r][t];
            run_sum[t] = run_sum[t] * s_scale[t] + cs;
        }
        __syncthreads();
    }

    if (t < BT) {
        g_pmax[split * M + m0 + t] = run_max[t];
        g_psum[split * M + m0 + t] = run_sum[t];
    }
}

// ---------------------------------------------------------------------------
// Combine the NSPLIT partials per m, apply the -b2 shift, reduce mean.
// ---------------------------------------------------------------------------
__global__ void zero_acc_kernel() { g_acc = 0.0f; }

__global__ void combine_kernel(const void* __restrict__ sigp, int M) {
    const int m = blockIdx.x * blockDim.x + threadIdx.x;
    float lse = 0.0f;
    if (m < M) {
        float gm = -INFINITY;
        #pragma unroll
        for (int s = 0; s < NSPLIT; ++s) gm = fmaxf(gm, g_pmax[s * M + m]);
        float sum = 0.0f;
        #pragma unroll
        for (int s = 0; s < NSPLIT; ++s)
            sum += g_psum[s * M + m] * __expf(g_pmax[s * M + m] - gm);
        const float sg     = load_sigma(sigp);
        const float inv2s2 = 1.0f / (2.0f * sg * sg);
        lse = logf(sum) + gm - g_b2[m] * inv2s2;
    }
    __shared__ float sh[256];
    sh[threadIdx.x] = lse;
    __syncthreads();
    #pragma unroll
    for (int o = 128; o; o >>= 1) {
        if (threadIdx.x < o) sh[threadIdx.x] += sh[threadIdx.x + o];
        __syncthreads();
    }
    if (threadIdx.x == 0) atomicAdd(&g_acc, sh[0]);
}

__global__ void finalize_kernel(float* out, int M) {
    out[0] = -g_acc / (float)M;
}

// ---------------------------------------------------------------------------
extern "C" void kernel_launch(void* const* d_in, const int* in_sizes, int n_in,
                              void* d_out, int out_size)
{
    const float* mean = (const float*)d_in[0];
    const float* e    = (const float*)d_in[1];
    const void*  sig  = d_in[2];
    float*       out  = (float*)d_out;

    const int N = in_sizes[0] / ZD;   // 32768
    const int M = in_sizes[1] / ZD;   // 8192

    zero_acc_kernel<<<1, 1>>>();

    {   // row norms (one warp per row, 8 warps / block)
        int blocksA = (N * 32 + 255) / 256;
        int blocksB = (M * 32 + 255) / 256;
        rownorm_a_kernel<<<blocksA, 256>>>(mean, N);
        rownorm_b_kernel<<<blocksB, 256>>>(e, M);
    }

    {   // fused GEMM + online LSE
        dim3 grid(M / BT, NSPLIT);
        gemm_lse_kernel<<<grid, 256>>>(mean, e, sig, N, M);
    }

    combine_kernel<<<(M + 255) / 256, 256>>>(sig, M);
    finalize_kernel<<<1, 1>>>(out, M);
}

// round 5
// speedup vs baseline: 3.2437x; 3.2437x over previous
#include <cuda_runtime.h>
#include <cstdint>
#include <math.h>

// ===========================================================================
// Problem constants
// ===========================================================================
#define ZD      256      // Z_DIM (K)
#define NSPLIT  16       // split of N across blockIdx.y
#define NSLOT   (NSPLIT * 4)   // 4 warp_n partials per split
#define MAXN    32768
#define MAXM    8192
#define CTAM    128      // e rows per CTA
#define CTAN    256      // mean rows per n-chunk
#define KC      32       // K per pipelined chunk
#define THREADS 256

// smem layout (bytes)
#define E_STRIDE   1056                       // 256 floats + pad (stride ≡ 8 mod 32 words)
#define M_STRIDE   160                        // 32 floats + pad  (stride ≡ 8 mod 32 words)
#define SM_E       0
#define E_BYTES    (CTAM * E_STRIDE)          // 135168
#define SM_MEAN    E_BYTES
#define MEAN_BUF   (CTAN * M_STRIDE)          // 40960
#define SMEM_TOTAL (SM_MEAN + 2 * MEAN_BUF)   // 217088

// Scratch (no allocations allowed)
__device__ float g_a2s[MAXN];            // cL * ||mean_n||^2   (base-2 units)
__device__ float g_b2[MAXM];             // ||e_m||^2 (raw)
__device__ float g_pmax[NSLOT * MAXM];
__device__ float g_psum[NSLOT * MAXM];
__device__ float g_acc;

// ===========================================================================
// helpers
// ===========================================================================
__device__ __forceinline__ uint32_t smem_u32(const void* p) {
    uint32_t a;
    asm("{ .reg .u64 t; cvta.to.shared.u64 t, %1; cvt.u32.u64 %0, t; }" : "=r"(a) : "l"(p));
    return a;
}
__device__ __forceinline__ void lds64(uint32_t& x, uint32_t& y, uint32_t addr) {
    asm volatile("ld.shared.v2.b32 {%0,%1}, [%2];" : "=r"(x), "=r"(y) : "r"(addr));
}
#define STS64(addr, x, y) \
    asm volatile("st.shared.v2.b32 [%0], {%1,%2};" :: "r"(addr), "r"(x), "r"(y) : "memory")

__device__ __forceinline__ uint32_t tf(float v) {
    float y; asm("cvt.rna.tf32.f32 %0, %1;" : "=f"(y) : "f"(v));
    return __float_as_uint(y);
}

// m16n8k8 tf32 mma: D += A*B  (A row-major m x k, B col-major k x n)
__device__ __forceinline__ void mma8(float* d, uint32_t a0, uint32_t a1,
                                     uint32_t a2, uint32_t a3,
                                     uint32_t b0, uint32_t b1) {
    asm volatile(
        "mma.sync.aligned.m16n8k8.row.col.f32.tf32.tf32.f32 "
        "{%0,%1,%2,%3}, {%4,%5,%6,%7}, {%8,%9}, {%0,%1,%2,%3};"
        : "+f"(d[0]), "+f"(d[1]), "+f"(d[2]), "+f"(d[3])
        : "r"(a0), "r"(a1), "r"(a2), "r"(a3), "r"(b0), "r"(b1));
}

// Fast 2^x on FMA/ALU pipes only (x <= 0 expected; clamped). |rel err| ~ 2e-8.
__device__ __forceinline__ float ex2p(float x) {
    x = fmaxf(x, -126.0f);
    float t, r;
    asm("add.rn.f32 %0, %1, 0f4B400000;" : "=f"(t) : "f"(x));   // + 1.5*2^23
    asm("sub.rn.f32 %0, %1, 0f4B400000;" : "=f"(r) : "f"(t));   // round(x)
    float f = x - r;                                            // [-0.5, 0.5]
    int   ir = __float_as_int(t) - 0x4B400000;                  // (int)r
    float p =            1.3333558146e-3f;
    p = fmaf(p, f, 9.6181291776e-3f);
    p = fmaf(p, f, 5.5504108664e-2f);
    p = fmaf(p, f, 2.4022650696e-1f);
    p = fmaf(p, f, 6.9314718056e-1f);
    p = fmaf(p, f, 1.0f);
    return p * __int_as_float((ir + 127) << 23);
}

// sigma dtype heuristic (float bits vs int)
__device__ __forceinline__ float load_sigma(const void* p) {
    int   i = *(const int*)p;
    float f = __int_as_float(i);
    if (isfinite(f) && fabsf(f) >= 1e-10f && fabsf(f) <= 1e10f) return f;
    return (float)i;
}

// ===========================================================================
// Row squared-norm kernels
// ===========================================================================
__global__ void rownorm_a_kernel(const float* __restrict__ X, const void* sigp, int rows) {
    int w = (blockIdx.x * blockDim.x + threadIdx.x) >> 5;
    int lane = threadIdx.x & 31;
    if (w >= rows) return;
    const float4* r = (const float4*)(X + (size_t)w * ZD);
    float s = 0.f;
    #pragma unroll
    for (int c = lane; c < ZD / 4; c += 32) {
        float4 v = r[c];
        s += v.x * v.x + v.y * v.y + v.z * v.z + v.w * v.w;
    }
    #pragma unroll
    for (int o = 16; o; o >>= 1) s += __shfl_xor_sync(0xffffffffu, s, o);
    if (lane == 0) {
        float sg = load_sigma(sigp);
        float cL = (1.0f / (2.0f * sg * sg)) * 1.4426950408889634f;
        g_a2s[w] = cL * s;
    }
}
__global__ void rownorm_b_kernel(const float* __restrict__ X, int rows) {
    int w = (blockIdx.x * blockDim.x + threadIdx.x) >> 5;
    int lane = threadIdx.x & 31;
    if (w >= rows) return;
    const float4* r = (const float4*)(X + (size_t)w * ZD);
    float s = 0.f;
    #pragma unroll
    for (int c = lane; c < ZD / 4; c += 32) {
        float4 v = r[c];
        s += v.x * v.x + v.y * v.y + v.z * v.z + v.w * v.w;
    }
    #pragma unroll
    for (int o = 16; o; o >>= 1) s += __shfl_xor_sync(0xffffffffu, s, o);
    if (lane == 0) g_b2[w] = s;
}

// ===========================================================================
// Main: mma.sync tf32 GEMM (e @ mean^T) fused with online base-2 LSE.
// CTA tile 128(m) x 256(n); 8 warps, warp tile 64x64; K pipelined in KC=32.
// k within each 8-group is pair-permuted [k0 k4 k1 k5 k2 k6 k3 k7] so every
// fragment (A and B) is a single LDS.64.
// ===========================================================================
__global__ __launch_bounds__(THREADS, 1)
void mma_lse_kernel(const float* __restrict__ mean,
                    const float* __restrict__ e,
                    const void* __restrict__ sigp,
                    int N, int M)
{
    extern __shared__ char smem[];
    const uint32_t sbase = smem_u32(smem);
    const int tid    = threadIdx.x;
    const int lane   = tid & 31;
    const int wid    = tid >> 5;
    const int warp_m = wid & 1;        // 0..1  (64 m-rows each)
    const int warp_n = wid >> 1;       // 0..3  (64 n-cols each)
    const int m0     = blockIdx.x * CTAM;
    const int split  = blockIdx.y;
    const int per_split = N / NSPLIT;          // 2048
    const int n_begin   = split * per_split;
    const int nchunks   = per_split / CTAN;    // 8
    const int total_it  = nchunks * (ZD / KC); // 64

    const float sg    = load_sigma(sigp);
    const float cL    = (1.0f / (2.0f * sg * sg)) * 1.4426950408889634f;
    const float twoCL = 2.0f * cL;

    // -------- prologue: e tile (whole K), tf32-converted, pair-permuted ----
    {
        #pragma unroll
        for (int i = 0; i < 16; ++i) {
            int u  = tid + i * 256;          // 0..4095
            int r  = u >> 5;                 // row 0..127
            int gg = u & 31;                 // k8-group 0..31
            const float4* src = (const float4*)(e + (size_t)(m0 + r) * ZD + gg * 8);
            float4 A = __ldg(src), B = __ldg(src + 1);
            uint32_t addr = sbase + SM_E + r * E_STRIDE + gg * 32;
            STS64(addr,      tf(A.x), tf(B.x));
            STS64(addr + 8,  tf(A.y), tf(B.y));
            STS64(addr + 16, tf(A.z), tf(B.z));
            STS64(addr + 24, tf(A.w), tf(B.w));
        }
    }
    // -------- prologue: mean chunk it=0 into buf 0 -------------------------
    {
        #pragma unroll
        for (int i = 0; i < 4; ++i) {
            int u = tid + i * 256;           // 0..1023
            int r = u >> 2, g = u & 3;
            const float4* src = (const float4*)(mean + (size_t)(n_begin + r) * ZD + g * 8);
            float4 A = __ldg(src), B = __ldg(src + 1);
            uint32_t addr = sbase + SM_MEAN + r * M_STRIDE + g * 32;
            STS64(addr,      tf(A.x), tf(B.x));
            STS64(addr + 8,  tf(A.y), tf(B.y));
            STS64(addr + 16, tf(A.z), tf(B.z));
            STS64(addr + 24, tf(A.w), tf(B.w));
        }
    }
    __syncthreads();

    float acc[4][8][4];
    #pragma unroll
    for (int mt = 0; mt < 4; ++mt)
        #pragma unroll
        for (int nt = 0; nt < 8; ++nt)
            #pragma unroll
            for (int i = 0; i < 4; ++i) acc[mt][nt][i] = 0.0f;

    float run_max[8], run_sum[8];
    #pragma unroll
    for (int i = 0; i < 8; ++i) { run_max[i] = -INFINITY; run_sum[i] = 0.0f; }

    const uint32_t p8       = (lane & 3) * 8;
    const uint32_t eRowBase = sbase + SM_E + (warp_m * 64 + (lane >> 2)) * E_STRIDE;
    const uint32_t mRowOff  = (warp_n * 64 + (lane >> 2)) * M_STRIDE;

    for (int it = 0; it < total_it; ++it) {
        const int kc  = it & 7;
        const int buf = it & 1;

        // ---- prefetch next chunk's gmem data into regs --------------------
        float4 pfA[4], pfB[4];
        const bool havePf = (it + 1 < total_it);
        if (havePf) {
            int nnc = (it + 1) >> 3, nkc = (it + 1) & 7;
            int nn0 = n_begin + nnc * CTAN;
            #pragma unroll
            for (int i = 0; i < 4; ++i) {
                int u = tid + i * 256;
                int r = u >> 2, g = u & 3;
                const float4* src =
                    (const float4*)(mean + (size_t)(nn0 + r) * ZD + nkc * KC + g * 8);
                pfA[i] = __ldg(src); pfB[i] = __ldg(src + 1);
            }
        }

        // ---- compute: KC=32 -> 4 k8 groups --------------------------------
        const uint32_t mBufBase = sbase + SM_MEAN + buf * MEAN_BUF + mRowOff;
        #pragma unroll
        for (int g = 0; g < 4; ++g) {
            const uint32_t kOffE = (uint32_t)((kc * 4 + g) * 32) + p8;
            const uint32_t kOffM = (uint32_t)(g * 32) + p8;
            uint32_t b0[8], b1[8];
            #pragma unroll
            for (int nt = 0; nt < 8; ++nt)
                lds64(b0[nt], b1[nt], mBufBase + nt * 8 * M_STRIDE + kOffM);
            #pragma unroll
            for (int mt = 0; mt < 4; ++mt) {
                uint32_t a0, a1, a2, a3;
                uint32_t addr = eRowBase + mt * 16 * E_STRIDE + kOffE;
                lds64(a0, a2, addr);
                lds64(a1, a3, addr + 8 * E_STRIDE);
                #pragma unroll
                for (int nt = 0; nt < 8; ++nt)
                    mma8(acc[mt][nt], a0, a1, a2, a3, b0[nt], b1[nt]);
            }
        }

        // ---- store prefetched data into the other buffer ------------------
        if (havePf) {
            uint32_t dstBuf = sbase + SM_MEAN + ((it + 1) & 1) * MEAN_BUF;
            #pragma unroll
            for (int i = 0; i < 4; ++i) {
                int u = tid + i * 256;
                int r = u >> 2, g = u & 3;
                uint32_t addr = dstBuf + r * M_STRIDE + g * 32;
                STS64(addr,      tf(pfA[i].x), tf(pfB[i].x));
                STS64(addr + 8,  tf(pfA[i].y), tf(pfB[i].y));
                STS64(addr + 16, tf(pfA[i].z), tf(pfB[i].z));
                STS64(addr + 24, tf(pfA[i].w), tf(pfB[i].w));
            }
        }
        __syncthreads();

        // ---- per-chunk LSE epilogue (thread-local, register-resident) -----
        if (kc == 7) {
            const int nc = it >> 3;
            const int n0 = n_begin + nc * CTAN + warp_n * 64 + (lane & 3) * 2;
            float a2v[8][2];
            #pragma unroll
            for (int nt = 0; nt < 8; ++nt) {
                a2v[nt][0] = __ldg(&g_a2s[n0 + nt * 8 + 0]);
                a2v[nt][1] = __ldg(&g_a2s[n0 + nt * 8 + 1]);
            }
            #pragma unroll
            for (int mt = 0; mt < 4; ++mt) {
                #pragma unroll
                for (int half = 0; half < 2; ++half) {
                    const int ridx = mt * 2 + half;
                    float bm = -INFINITY;
                    #pragma unroll
                    for (int nt = 0; nt < 8; ++nt) {
                        #pragma unroll
                        for (int j = 0; j < 2; ++j) {
                            float w = fmaf(acc[mt][nt][half * 2 + j], twoCL, -a2v[nt][j]);
                            acc[mt][nt][half * 2 + j] = w;
                            bm = fmaxf(bm, w);
                        }
                    }
                    float nm = fmaxf(run_max[ridx], bm);
                    float sc = ex2p(run_max[ridx] - nm);
                    float s  = 0.0f;
                    #pragma unroll
                    for (int nt = 0; nt < 8; ++nt) {
                        s += ex2p(acc[mt][nt][half * 2 + 0] - nm);
                        s += ex2p(acc[mt][nt][half * 2 + 1] - nm);
                        acc[mt][nt][half * 2 + 0] = 0.0f;
                        acc[mt][nt][half * 2 + 1] = 0.0f;
                    }
                    run_sum[ridx] = fmaf(run_sum[ridx], sc, s);
                    run_max[ridx] = nm;
                }
            }
        }
    }

    // -------- quad reduction (lanes of a quad hold different n-cols of the
    //          same rows) and partial writeout ------------------------------
    #pragma unroll
    for (int ridx = 0; ridx < 8; ++ridx) {
        float m1 = run_max[ridx], s1 = run_sum[ridx];
        #pragma unroll
        for (int o = 1; o <= 2; o <<= 1) {
            float m2 = __shfl_xor_sync(0xffffffffu, m1, o);
            float s2 = __shfl_xor_sync(0xffffffffu, s1, o);
            float nm = fmaxf(m1, m2);
            s1 = s1 * ex2p(m1 - nm) + s2 * ex2p(m2 - nm);
            m1 = nm;
        }
        if ((lane & 3) == 0) {
            int mrow = m0 + warp_m * 64 + (ridx >> 1) * 16 + (ridx & 1) * 8 + (lane >> 2);
            int slot = split * 4 + warp_n;
            g_pmax[slot * M + mrow] = m1;
            g_psum[slot * M + mrow] = s1;
        }
    }
}

// ===========================================================================
// Reduction tail
// ===========================================================================
__global__ void zero_acc_kernel() { g_acc = 0.0f; }

__global__ void combine_kernel(const void* __restrict__ sigp, int M) {
    const int m = blockIdx.x * blockDim.x + threadIdx.x;
    float v = 0.0f;
    if (m < M) {
        float gm = -INFINITY;
        for (int s = 0; s < NSLOT; ++s) gm = fmaxf(gm, g_pmax[s * M + m]);
        float sum = 0.0f;
        for (int s = 0; s < NSLOT; ++s)
            sum += g_psum[s * M + m] * ex2p(g_pmax[s * M + m] - gm);
        const float sg = load_sigma(sigp);
        const float cL = (1.0f / (2.0f * sg * sg)) * 1.4426950408889634f;
        v = 0.69314718055994531f * (gm - cL * g_b2[m]) + logf(sum);
    }
    __shared__ float sh[256];
    sh[threadIdx.x] = v;
    __syncthreads();
    #pragma unroll
    for (int o = 128; o; o >>= 1) {
        if (threadIdx.x < o) sh[threadIdx.x] += sh[threadIdx.x + o];
        __syncthreads();
    }
    if (threadIdx.x == 0) atomicAdd(&g_acc, sh[0]);
}

__global__ void finalize_kernel(float* out, int M) {
    out[0] = -g_acc / (float)M;
}

// ===========================================================================
extern "C" void kernel_launch(void* const* d_in, const int* in_sizes, int n_in,
                              void* d_out, int out_size)
{
    const float* mean = (const float*)d_in[0];
    const float* e    = (const float*)d_in[1];
    const void*  sig  = d_in[2];
    float*       out  = (float*)d_out;

    const int N = in_sizes[0] / ZD;   // 32768
    const int M = in_sizes[1] / ZD;   // 8192

    cudaFuncSetAttribute(mma_lse_kernel,
                         cudaFuncAttributeMaxDynamicSharedMemorySize, SMEM_TOTAL);

    zero_acc_kernel<<<1, 1>>>();
    rownorm_a_kernel<<<(N * 32 + 255) / 256, 256>>>(mean, sig, N);
    rownorm_b_kernel<<<(M * 32 + 255) / 256, 256>>>(e, M);

    dim3 grid(M / CTAM, NSPLIT);
    mma_lse_kernel<<<grid, THREADS, SMEM_TOTAL>>>(mean, e, sig, N, M);

    combine_kernel<<<(M + 255) / 256, 256>>>(sig, M);
    finalize_kernel<<<1, 1>>>(out, M);
}

// round 6
// speedup vs baseline: 3.7035x; 1.1418x over previous
#include <cuda_runtime.h>
#include <cstdint>
#include <math.h>

// ===========================================================================
// Problem constants
// ===========================================================================
#define ZD      256      // Z_DIM (K)
#define NSPLIT  16       // split of N across blockIdx.y
#define NSLOT   (NSPLIT * 4)   // 4 warp_n partials per split
#define MAXN    32768
#define MAXM    8192
#define CTAM    128      // e rows per CTA
#define CTAN    256      // mean rows per n-chunk
#define KC      32       // K per pipelined chunk
#define THREADS 256

// smem layout (bytes)
#define E_STRIDE   1056                       // 256 floats + pad (stride ≡ 8 mod 32 words)
#define M_STRIDE   160                        // 32 floats + pad  (stride ≡ 8 mod 32 words)
#define SM_E       0
#define E_BYTES    (CTAM * E_STRIDE)          // 135168
#define SM_MEAN    E_BYTES
#define MEAN_BUF   (CTAN * M_STRIDE)          // 40960
#define SMEM_TOTAL (SM_MEAN + 2 * MEAN_BUF)   // 217088

// Scratch (no allocations allowed -> __device__ globals)
__device__ float g_mean_tf[(size_t)MAXN * ZD];   // tf32-converted, pair-permuted
__device__ float g_e_tf[(size_t)MAXM * ZD];      // tf32-converted, pair-permuted
__device__ float g_a2s[MAXN];            // cL * ||mean_n||^2   (base-2 units)
__device__ float g_b2[MAXM];             // ||e_m||^2 (raw)
__device__ float g_pmax[NSLOT * MAXM];
__device__ float g_psum[NSLOT * MAXM];
__device__ float g_acc;

// ===========================================================================
// helpers
// ===========================================================================
__device__ __forceinline__ uint32_t smem_u32(const void* p) {
    uint32_t a;
    asm("{ .reg .u64 t; cvta.to.shared.u64 t, %1; cvt.u32.u64 %0, t; }" : "=r"(a) : "l"(p));
    return a;
}
__device__ __forceinline__ void lds64(uint32_t& x, uint32_t& y, uint32_t addr) {
    asm volatile("ld.shared.v2.b32 {%0,%1}, [%2];" : "=r"(x), "=r"(y) : "r"(addr));
}
#define CP_ASYNC16(dst, src) \
    asm volatile("cp.async.cg.shared.global [%0], [%1], 16;" :: "r"(dst), "l"(src) : "memory")
#define CP_COMMIT() asm volatile("cp.async.commit_group;" ::: "memory")
#define CP_WAIT0()  asm volatile("cp.async.wait_group 0;" ::: "memory")

__device__ __forceinline__ float tfv(float v) {
    float y; asm("cvt.rna.tf32.f32 %0, %1;" : "=f"(y) : "f"(v));
    return y;
}

// m16n8k8 tf32 mma: D += A*B  (A row-major m x k, B col-major k x n)
__device__ __forceinline__ void mma8(float* d, uint32_t a0, uint32_t a1,
                                     uint32_t a2, uint32_t a3,
                                     uint32_t b0, uint32_t b1) {
    asm volatile(
        "mma.sync.aligned.m16n8k8.row.col.f32.tf32.tf32.f32 "
        "{%0,%1,%2,%3}, {%4,%5,%6,%7}, {%8,%9}, {%0,%1,%2,%3};"
        : "+f"(d[0]), "+f"(d[1]), "+f"(d[2]), "+f"(d[3])
        : "r"(a0), "r"(a1), "r"(a2), "r"(a3), "r"(b0), "r"(b1));
}

// Fast 2^x on FMA/ALU pipes only (x <= 0 expected; clamped). |rel err| ~ 2e-8.
__device__ __forceinline__ float ex2p(float x) {
    x = fmaxf(x, -126.0f);
    float t, r;
    asm("add.rn.f32 %0, %1, 0f4B400000;" : "=f"(t) : "f"(x));   // + 1.5*2^23
    asm("sub.rn.f32 %0, %1, 0f4B400000;" : "=f"(r) : "f"(t));   // round(x)
    float f = x - r;                                            // [-0.5, 0.5]
    int   ir = __float_as_int(t) - 0x4B400000;                  // (int)r
    float p =            1.3333558146e-3f;
    p = fmaf(p, f, 9.6181291776e-3f);
    p = fmaf(p, f, 5.5504108664e-2f);
    p = fmaf(p, f, 2.4022650696e-1f);
    p = fmaf(p, f, 6.9314718056e-1f);
    p = fmaf(p, f, 1.0f);
    return p * __int_as_float((ir + 127) << 23);
}

// sigma dtype heuristic (float bits vs int)
__device__ __forceinline__ float load_sigma(const void* p) {
    int   i = *(const int*)p;
    float f = __int_as_float(i);
    if (isfinite(f) && fabsf(f) >= 1e-10f && fabsf(f) <= 1e10f) return f;
    return (float)i;
}

// ===========================================================================
// Pre-pass: row squared-norms + tf32 conversion with k-pair permutation.
// One warp per row; lane g handles k8-group g: loads k[8g..8g+7] as two
// float4s (A, B) and stores interleaved (Ax,Bx,Ay,By,Az,Bz,Aw,Bw), i.e. the
// [k0 k4 k1 k5 k2 k6 k3 k7] permutation that makes every MMA fragment one
// LDS.64 in the main kernel.
// ===========================================================================
__global__ void prep_a_kernel(const float* __restrict__ X, const void* sigp, int rows) {
    int w = (blockIdx.x * blockDim.x + threadIdx.x) >> 5;
    int lane = threadIdx.x & 31;
    if (w >= rows) return;
    const float4* r = (const float4*)(X + (size_t)w * ZD);
    float4 A = __ldg(r + 2 * lane), B = __ldg(r + 2 * lane + 1);
    float s = A.x * A.x + A.y * A.y + A.z * A.z + A.w * A.w
            + B.x * B.x + B.y * B.y + B.z * B.z + B.w * B.w;
    #pragma unroll
    for (int o = 16; o; o >>= 1) s += __shfl_xor_sync(0xffffffffu, s, o);
    if (lane == 0) {
        float sg = load_sigma(sigp);
        float cL = (1.0f / (2.0f * sg * sg)) * 1.4426950408889634f;
        g_a2s[w] = cL * s;
    }
    float4* dst = (float4*)(g_mean_tf + (size_t)w * ZD + lane * 8);
    dst[0] = make_float4(tfv(A.x), tfv(B.x), tfv(A.y), tfv(B.y));
    dst[1] = make_float4(tfv(A.z), tfv(B.z), tfv(A.w), tfv(B.w));
}
__global__ void prep_b_kernel(const float* __restrict__ X, int rows) {
    int w = (blockIdx.x * blockDim.x + threadIdx.x) >> 5;
    int lane = threadIdx.x & 31;
    if (w >= rows) return;
    const float4* r = (const float4*)(X + (size_t)w * ZD);
    float4 A = __ldg(r + 2 * lane), B = __ldg(r + 2 * lane + 1);
    float s = A.x * A.x + A.y * A.y + A.z * A.z + A.w * A.w
            + B.x * B.x + B.y * B.y + B.z * B.z + B.w * B.w;
    #pragma unroll
    for (int o = 16; o; o >>= 1) s += __shfl_xor_sync(0xffffffffu, s, o);
    if (lane == 0) g_b2[w] = s;
    float4* dst = (float4*)(g_e_tf + (size_t)w * ZD + lane * 8);
    dst[0] = make_float4(tfv(A.x), tfv(B.x), tfv(A.y), tfv(B.y));
    dst[1] = make_float4(tfv(A.z), tfv(B.z), tfv(A.w), tfv(B.w));
}

// ===========================================================================
// Main: mma.sync tf32 GEMM (e @ mean^T) fused with online base-2 LSE.
// CTA tile 128(m) x 256(n); 8 warps, warp tile 64x64; K pipelined in KC=32
// via cp.async double buffering from the pre-converted global copies.
// ===========================================================================
__global__ __launch_bounds__(THREADS, 1)
void mma_lse_kernel(const void* __restrict__ sigp, int N, int M)
{
    extern __shared__ char smem[];
    const uint32_t sbase = smem_u32(smem);
    const int tid    = threadIdx.x;
    const int lane   = tid & 31;
    const int wid    = tid >> 5;
    const int warp_m = wid & 1;        // 0..1  (64 m-rows each)
    const int warp_n = wid >> 1;       // 0..3  (64 n-cols each)
    const int m0     = blockIdx.x * CTAM;
    const int split  = blockIdx.y;
    const int per_split = N / NSPLIT;          // 2048
    const int n_begin   = split * per_split;
    const int nchunks   = per_split / CTAN;    // 8
    const int total_it  = nchunks * (ZD / KC); // 64

    const float sg    = load_sigma(sigp);
    const float cL    = (1.0f / (2.0f * sg * sg)) * 1.4426950408889634f;
    const float twoCL = 2.0f * cL;

    const char* ebase = (const char*)g_e_tf;
    const char* mbase = (const char*)g_mean_tf;

    // -------- prologue: e tile (whole K) + mean chunk 0 via cp.async -------
    {
        // e: 128 rows x 1024B = 8192 x 16B chunks; 32 per thread
        #pragma unroll
        for (int i = 0; i < 32; ++i) {
            int u = tid + i * 256;
            int r = u >> 6;                 // row 0..127
            int c = u & 63;                 // 16B chunk in row
            uint32_t dst = sbase + SM_E + r * E_STRIDE + c * 16;
            const char* src = ebase + ((size_t)(m0 + r) << 10) + c * 16;
            CP_ASYNC16(dst, src);
        }
        // mean chunk 0 (nc=0, kc=0): 256 rows x 128B = 2048 x 16B; 8/thread
        #pragma unroll
        for (int i = 0; i < 8; ++i) {
            int u = tid + i * 256;
            int r = u >> 3;
            int c = u & 7;
            uint32_t dst = sbase + SM_MEAN + r * M_STRIDE + c * 16;
            const char* src = mbase + ((size_t)(n_begin + r) << 10) + c * 16;
            CP_ASYNC16(dst, src);
        }
        CP_COMMIT();
        CP_WAIT0();
    }
    __syncthreads();

    float acc[4][8][4];
    #pragma unroll
    for (int mt = 0; mt < 4; ++mt)
        #pragma unroll
        for (int nt = 0; nt < 8; ++nt)
            #pragma unroll
            for (int i = 0; i < 4; ++i) acc[mt][nt][i] = 0.0f;

    float run_max[8], run_sum[8];
    #pragma unroll
    for (int i = 0; i < 8; ++i) { run_max[i] = -INFINITY; run_sum[i] = 0.0f; }

    const uint32_t p8       = (lane & 3) * 8;
    const uint32_t eRowBase = sbase + SM_E + (warp_m * 64 + (lane >> 2)) * E_STRIDE;
    const uint32_t mRowOff  = (warp_n * 64 + (lane >> 2)) * M_STRIDE;

    for (int it = 0; it < total_it; ++it) {
        const int kc  = it & 7;
        const int buf = it & 1;

        // ---- issue async copy of next chunk into the other buffer ---------
        const bool havePf = (it + 1 < total_it);
        if (havePf) {
            int nnc = (it + 1) >> 3, nkc = (it + 1) & 7;
            int nn0 = n_begin + nnc * CTAN;
            uint32_t dstBuf = sbase + SM_MEAN + ((it + 1) & 1) * MEAN_BUF;
            #pragma unroll
            for (int i = 0; i < 8; ++i) {
                int u = tid + i * 256;
                int r = u >> 3;
                int c = u & 7;
                uint32_t dst = dstBuf + r * M_STRIDE + c * 16;
                const char* src = mbase + ((size_t)(nn0 + r) << 10) + nkc * 128 + c * 16;
                CP_ASYNC16(dst, src);
            }
        }
        CP_COMMIT();

        // ---- compute: KC=32 -> 4 k8 groups --------------------------------
        const uint32_t mBufBase = sbase + SM_MEAN + buf * MEAN_BUF + mRowOff;
        #pragma unroll
        for (int g = 0; g < 4; ++g) {
            const uint32_t kOffE = (uint32_t)((kc * 4 + g) * 32) + p8;
            const uint32_t kOffM = (uint32_t)(g * 32) + p8;
            uint32_t b0[8], b1[8];
            #pragma unroll
            for (int nt = 0; nt < 8; ++nt)
                lds64(b0[nt], b1[nt], mBufBase + nt * 8 * M_STRIDE + kOffM);
            #pragma unroll
            for (int mt = 0; mt < 4; ++mt) {
                uint32_t a0, a1, a2, a3;
                uint32_t addr = eRowBase + mt * 16 * E_STRIDE + kOffE;
                lds64(a0, a2, addr);
                lds64(a1, a3, addr + 8 * E_STRIDE);
                #pragma unroll
                for (int nt = 0; nt < 8; ++nt)
                    mma8(acc[mt][nt], a0, a1, a2, a3, b0[nt], b1[nt]);
            }
        }

        // ---- per-chunk LSE epilogue (thread-local, register-resident) -----
        if (kc == 7) {
            const int nc = it >> 3;
            const int n0 = n_begin + nc * CTAN + warp_n * 64 + (lane & 3) * 2;
            float a2v[8][2];
            #pragma unroll
            for (int nt = 0; nt < 8; ++nt) {
                a2v[nt][0] = __ldg(&g_a2s[n0 + nt * 8 + 0]);
                a2v[nt][1] = __ldg(&g_a2s[n0 + nt * 8 + 1]);
            }
            #pragma unroll
            for (int mt = 0; mt < 4; ++mt) {
                #pragma unroll
                for (int half = 0; half < 2; ++half) {
                    const int ridx = mt * 2 + half;
                    float bm = -INFINITY;
                    #pragma unroll
                    for (int nt = 0; nt < 8; ++nt) {
                        #pragma unroll
                        for (int j = 0; j < 2; ++j) {
                            float w = fmaf(acc[mt][nt][half * 2 + j], twoCL, -a2v[nt][j]);
                            acc[mt][nt][half * 2 + j] = w;
                            bm = fmaxf(bm, w);
                        }
                    }
                    float nm = fmaxf(run_max[ridx], bm);
                    float sc = ex2p(run_max[ridx] - nm);
                    float s  = 0.0f;
                    #pragma unroll
                    for (int nt = 0; nt < 8; ++nt) {
                        s += ex2p(acc[mt][nt][half * 2 + 0] - nm);
                        s += ex2p(acc[mt][nt][half * 2 + 1] - nm);
                        acc[mt][nt][half * 2 + 0] = 0.0f;
                        acc[mt][nt][half * 2 + 1] = 0.0f;
                    }
                    run_sum[ridx] = fmaf(run_sum[ridx], sc, s);
                    run_max[ridx] = nm;
                }
            }
        }

        CP_WAIT0();
        __syncthreads();
    }

    // -------- quad reduction (lanes of a quad hold different n-cols of the
    //          same rows) and partial writeout ------------------------------
    #pragma unroll
    for (int ridx = 0; ridx < 8; ++ridx) {
        float m1 = run_max[ridx], s1 = run_sum[ridx];
        #pragma unroll
        for (int o = 1; o <= 2; o <<= 1) {
            float m2 = __shfl_xor_sync(0xffffffffu, m1, o);
            float s2 = __shfl_xor_sync(0xffffffffu, s1, o);
            float nm = fmaxf(m1, m2);
            s1 = s1 * ex2p(m1 - nm) + s2 * ex2p(m2 - nm);
            m1 = nm;
        }
        if ((lane & 3) == 0) {
            int mrow = m0 + warp_m * 64 + (ridx >> 1) * 16 + (ridx & 1) * 8 + (lane >> 2);
            int slot = split * 4 + warp_n;
            g_pmax[slot * M + mrow] = m1;
            g_psum[slot * M + mrow] = s1;
        }
    }
}

// ===========================================================================
// Reduction tail
// ===========================================================================
__global__ void zero_acc_kernel() { g_acc = 0.0f; }

__global__ void combine_kernel(const void* __restrict__ sigp, int M) {
    const int m = blockIdx.x * blockDim.x + threadIdx.x;
    float v = 0.0f;
    if (m < M) {
        float gm = -INFINITY;
        for (int s = 0; s < NSLOT; ++s) gm = fmaxf(gm, g_pmax[s * M + m]);
        float sum = 0.0f;
        for (int s = 0; s < NSLOT; ++s)
            sum += g_psum[s * M + m] * ex2p(g_pmax[s * M + m] - gm);
        const float sg = load_sigma(sigp);
        const float cL = (1.0f / (2.0f * sg * sg)) * 1.4426950408889634f;
        v = 0.69314718055994531f * (gm - cL * g_b2[m]) + logf(sum);
    }
    __shared__ float sh[256];
    sh[threadIdx.x] = v;
    __syncthreads();
    #pragma unroll
    for (int o = 128; o; o >>= 1) {
        if (threadIdx.x < o) sh[threadIdx.x] += sh[threadIdx.x + o];
        __syncthreads();
    }
    if (threadIdx.x == 0) atomicAdd(&g_acc, sh[0]);
}

__global__ void finalize_kernel(float* out, int M) {
    out[0] = -g_acc / (float)M;
}

// ===========================================================================
extern "C" void kernel_launch(void* const* d_in, const int* in_sizes, int n_in,
                              void* d_out, int out_size)
{
    const float* mean = (const float*)d_in[0];
    const float* e    = (const float*)d_in[1];
    const void*  sig  = d_in[2];
    float*       out  = (float*)d_out;

    const int N = in_sizes[0] / ZD;   // 32768
    const int M = in_sizes[1] / ZD;   // 8192

    cudaFuncSetAttribute(mma_lse_kernel,
                         cudaFuncAttributeMaxDynamicSharedMemorySize, SMEM_TOTAL);

    zero_acc_kernel<<<1, 1>>>();
    prep_a_kernel<<<(N * 32 + 255) / 256, 256>>>(mean, sig, N);
    prep_b_kernel<<<(M * 32 + 255) / 256, 256>>>(e, M);

    dim3 grid(M / CTAM, NSPLIT);
    mma_lse_kernel<<<grid, THREADS, SMEM_TOTAL>>>(sig, N, M);

    combine_kernel<<<(M + 255) / 256, 256>>>(sig, M);
    finalize_kernel<<<1, 1>>>(out, M);
}